// round 6
// baseline (speedup 1.0000x reference)
#include <cuda_runtime.h>
#include <cuda_bf16.h>
#include <cstdint>
#include <cstddef>

// Problem constants
#define T_STEPS 784
#define NBATCH  128
#define HID     512
#define OUTC    10
#define DECAY   0.2f
#define THRESH  0.5f
#define KDIM    512

// Time-chunk pipeline
#define TC    112            // 7 chunks of 112 (112 = 7*16)
#define NCHK  7

// GEMM tiling
#define BM 128
#define BN 128
#define BK 64
#define ROWB 144u              // smem bytes per row: 64 bf16 (128B) + 16B pad
#define TILEB (128u * ROWB)    // 18432 B
#define STAGEB (3u * TILEB)    // A + Wh + Wl per stage
#define GEMM_SMEM (2u * STAGEB)  // 110592 B double-buffered

// Recurrence pipelining
#define UNR 16                 // 112 = 7 * 16

#define SEQ_ELEMS ((size_t)T_STEPS * NBATCH * HID)
__device__ __nv_bfloat16 g_S1b[SEQ_ELEMS];   // layer-1 spikes [t][n][i] (exact 0/1)
__device__ __nv_bfloat16 g_S2b[SEQ_ELEMS];   // layer-2 spikes
__device__ float         g_C  [SEQ_ELEMS];   // GEMM-1 output [t][n][j] fp32
__device__ float         g_C2 [SEQ_ELEMS];   // GEMM-2 output (separate: overlap-safe)
__device__ __nv_bfloat16 g_W2h[HID*HID], g_W2l[HID*HID];
__device__ __nv_bfloat16 g_W3h[HID*HID], g_W3l[HID*HID];
__device__ float         g_maskT[3][T_STEPS * HID];   // transposed masks [T][H]
// Carried recurrence state per layer (index 0..2)
__device__ float g_mem[3][NBATCH*HID];
__device__ float g_spk[3][NBATCH*HID];
__device__ float g_ss [3][NBATCH*HID];

// ---------------------------------------------------------------------------
// PTX helpers
// ---------------------------------------------------------------------------
__device__ __forceinline__ uint32_t smem_u32(const void* p){
    uint32_t a;
    asm("{ .reg .u64 t; cvta.to.shared.u64 t, %1; cvt.u32.u64 %0, t; }" : "=r"(a) : "l"(p));
    return a;
}
__device__ __forceinline__ void cp16(uint32_t saddr, const void* gaddr){
    asm volatile("cp.async.cg.shared.global [%0], [%1], 16;" :: "r"(saddr), "l"(gaddr));
}
__device__ __forceinline__ void ldsm4(uint32_t* r, uint32_t addr){
    asm volatile("ldmatrix.sync.aligned.m8n8.x4.shared.b16 {%0,%1,%2,%3}, [%4];"
        : "=r"(r[0]), "=r"(r[1]), "=r"(r[2]), "=r"(r[3]) : "r"(addr));
}
__device__ __forceinline__ void mma_bf16(float* c, const uint32_t* a, const uint32_t* b){
    asm volatile(
        "mma.sync.aligned.m16n8k16.row.col.f32.bf16.bf16.f32 "
        "{%0,%1,%2,%3}, {%4,%5,%6,%7}, {%8,%9}, {%0,%1,%2,%3};"
        : "+f"(c[0]), "+f"(c[1]), "+f"(c[2]), "+f"(c[3])
        : "r"(a[0]), "r"(a[1]), "r"(a[2]), "r"(a[3]), "r"(b[0]), "r"(b[1]));
}

// ---------------------------------------------------------------------------
// Weight split: W -> hi(bf16) + lo(bf16)
// ---------------------------------------------------------------------------
__global__ void split_kernel(const float* __restrict__ W2, const float* __restrict__ W3){
    int idx = blockIdx.x * blockDim.x + threadIdx.x;
    if (idx < HID * HID){
        float w = W2[idx];
        __nv_bfloat16 h = __float2bfloat16(w);
        g_W2h[idx] = h;
        g_W2l[idx] = __float2bfloat16(w - __bfloat162float(h));
        w = W3[idx];
        h = __float2bfloat16(w);
        g_W3h[idx] = h;
        g_W3l[idx] = __float2bfloat16(w - __bfloat162float(h));
    }
}

// ---------------------------------------------------------------------------
// Mask transpose: [H][T] -> [T][H]
// ---------------------------------------------------------------------------
__global__ void maskT_kernel(const float* __restrict__ m1,
                             const float* __restrict__ m2,
                             const float* __restrict__ m3)
{
    __shared__ float tile[32][33];
    const float* src = (blockIdx.z == 0) ? m1 : (blockIdx.z == 1) ? m2 : m3;
    const int jb = blockIdx.x * 32;
    const int tb = blockIdx.y * 32;
    const int tx = threadIdx.x, ty = threadIdx.y;

    if (tb + tx < T_STEPS)
        tile[ty][tx] = src[(size_t)(jb + ty) * T_STEPS + tb + tx];
    __syncthreads();
    if (tb + ty < T_STEPS)
        g_maskT[blockIdx.z][(size_t)(tb + ty) * HID + jb + tx] = tile[tx][ty];
}

// ---------------------------------------------------------------------------
// Layer-1 recurrence chunk: t in [c*TC, (c+1)*TC).
// grid (NBATCH, HID/128), block 128. 16-step register double-buffer.
// ---------------------------------------------------------------------------
__global__ void layer1_kernel(const float* __restrict__ x,
                              const float* __restrict__ W1,
                              const float* __restrict__ b1,
                              float* __restrict__ fr1,
                              int c)
{
    const int n = blockIdx.x;
    const int i = blockIdx.y * 128 + threadIdx.x;
    const int sid = n * HID + i;
    const float w = W1[i];
    const float b = b1[i];
    const float* __restrict__ xr = x + (size_t)n * T_STEPS;
    const float* __restrict__ mk = g_maskT[0];
    __nv_bfloat16* __restrict__ sOut = g_S1b + (size_t)n * HID + i;
    const size_t cstr = (size_t)NBATCH * HID;
    const int t0 = c * TC;

    float mem, spike, ss;
    if (c == 0){ mem = 0.f; spike = 0.f; ss = 0.f; }
    else { mem = g_mem[0][sid]; spike = g_spk[0][sid]; ss = g_ss[0][sid]; }

    float xb[2][UNR], mb[2][UNR];
    #pragma unroll
    for (int u = 0; u < UNR; ++u){
        xb[0][u] = xr[t0 + u];
        mb[0][u] = mk[(size_t)(t0 + u) * HID + i];
    }

    for (int tc = 0; tc < TC / UNR; ++tc){
        const int cur = tc & 1, nxt = cur ^ 1;
        const int tb = t0 + tc * UNR;
        if (tc + 1 < TC / UNR){
            #pragma unroll
            for (int u = 0; u < UNR; ++u){
                xb[nxt][u] = xr[tb + UNR + u];
                mb[nxt][u] = mk[(size_t)(tb + UNR + u) * HID + i];
            }
        }
        #pragma unroll
        for (int u = 0; u < UNR; ++u){
            const float m_t = mb[cur][u];
            const float new_mem = mem * DECAY * (1.f - spike) + xb[cur][u] * w + b;
            if (m_t != 0.f) mem = new_mem;
            const float spk = (mem > THRESH) ? m_t : 0.f;
            sOut[(size_t)(tb + u) * cstr] = __float2bfloat16(spk);
            ss += spk;
            spike = spk;
        }
    }
    g_mem[0][sid] = mem; g_spk[0][sid] = spike; g_ss[0][sid] = ss;
    if (c == NCHK - 1) fr1[sid] = ss * (1.f / (float)T_STEPS);
}

// ---------------------------------------------------------------------------
// bf16 HMMA GEMM chunk: m-tiles t = cbase*TC + blockIdx.y.
// which: 0 -> A=g_S1b, C=g_C ; 1 -> A=g_S2b, C=g_C2.
// ---------------------------------------------------------------------------
__global__ void __launch_bounds__(256, 2)
gemm_bf16(int which, int cbase)
{
    extern __shared__ char smem[];
    const __nv_bfloat16* __restrict__ A  = which ? g_S2b : g_S1b;
    const __nv_bfloat16* __restrict__ Bh = which ? g_W3h : g_W2h;
    const __nv_bfloat16* __restrict__ Bl = which ? g_W3l : g_W2l;
    float* __restrict__ Cout = which ? g_C2 : g_C;

    const uint32_t sb = smem_u32(smem);
    const int tid  = threadIdx.x;
    const int lane = tid & 31;
    const int wrp  = tid >> 5;
    const int wm   = wrp & 1;          // 2 warp-rows of 64
    const int wn   = wrp >> 1;         // 4 warp-cols of 32
    const int n0 = blockIdx.x * BN;
    const int m0 = (cbase * TC + blockIdx.y) * BM;

    auto load_stage = [&](int st, int c){
        const uint32_t base = sb + (uint32_t)st * STAGEB;
        #pragma unroll
        for (int i = 0; i < 4; ++i){
            const int q   = tid + 256 * i;
            const int row = q >> 3;
            const int kc  = q & 7;
            const uint32_t soff = (uint32_t)row * ROWB + (uint32_t)kc * 16u;
            const size_t gk = (size_t)c * BK + (size_t)kc * 8;
            cp16(base + soff,             A  + (size_t)(m0 + row) * KDIM + gk);
            cp16(base + TILEB + soff,     Bh + (size_t)(n0 + row) * KDIM + gk);
            cp16(base + 2u*TILEB + soff,  Bl + (size_t)(n0 + row) * KDIM + gk);
        }
        asm volatile("cp.async.commit_group;" ::: "memory");
    };

    float acc[4][4][4];
    #pragma unroll
    for (int mi = 0; mi < 4; ++mi)
        #pragma unroll
        for (int ni = 0; ni < 4; ++ni)
            #pragma unroll
            for (int q = 0; q < 4; ++q) acc[mi][ni][q] = 0.f;

    const uint32_t aOff = (uint32_t)(wm * 64 + (lane & 15)) * ROWB
                        + (uint32_t)((lane >> 4) << 3) * 2u;
    const uint32_t bOff = (uint32_t)(wn * 32 + ((lane >> 4) << 3) + (lane & 7)) * ROWB
                        + (uint32_t)(((lane >> 3) & 1) << 4);

    load_stage(0, 0);

    const int NC = KDIM / BK;   // 8
    for (int c = 0; c < NC; ++c){
        if (c + 1 < NC){
            load_stage((c + 1) & 1, c + 1);
            asm volatile("cp.async.wait_group 1;" ::: "memory");
        } else {
            asm volatile("cp.async.wait_group 0;" ::: "memory");
        }
        __syncthreads();

        const uint32_t base = sb + (uint32_t)(c & 1) * STAGEB;
        const uint32_t aB = base + aOff;
        const uint32_t hB = base + TILEB + bOff;
        const uint32_t lB = base + 2u*TILEB + bOff;

        #pragma unroll
        for (int k16 = 0; k16 < 4; ++k16){
            uint32_t a[4][4], bh[2][4], bl[2][4];
            #pragma unroll
            for (int mi = 0; mi < 4; ++mi)
                ldsm4(a[mi], aB + (uint32_t)(mi * 16) * ROWB + (uint32_t)k16 * 32u);
            #pragma unroll
            for (int p = 0; p < 2; ++p){
                ldsm4(bh[p], hB + (uint32_t)(p * 16) * ROWB + (uint32_t)k16 * 32u);
                ldsm4(bl[p], lB + (uint32_t)(p * 16) * ROWB + (uint32_t)k16 * 32u);
            }
            #pragma unroll
            for (int mi = 0; mi < 4; ++mi)
                #pragma unroll
                for (int ni = 0; ni < 4; ++ni){
                    mma_bf16(acc[mi][ni], a[mi], &bh[ni >> 1][(ni & 1) * 2]);
                    mma_bf16(acc[mi][ni], a[mi], &bl[ni >> 1][(ni & 1) * 2]);
                }
        }
        __syncthreads();
    }

    const int rbase = m0 + wm * 64 + (lane >> 2);
    const int cbase2 = n0 + wn * 32 + (lane & 3) * 2;
    #pragma unroll
    for (int mi = 0; mi < 4; ++mi){
        #pragma unroll
        for (int ni = 0; ni < 4; ++ni){
            float* p0 = Cout + (size_t)(rbase + mi * 16) * HID + cbase2 + ni * 8;
            float* p1 = p0 + 8 * HID;
            *(float2*)p0 = make_float2(acc[mi][ni][0], acc[mi][ni][1]);
            *(float2*)p1 = make_float2(acc[mi][ni][2], acc[mi][ni][3]);
        }
    }
}

// ---------------------------------------------------------------------------
// Layer-2/3 recurrence chunk. layer==2: reads g_C, stores spikes to g_S2b.
// layer==3: reads g_C2, no spike store. State index = layer-1.
// ---------------------------------------------------------------------------
__global__ void layerR_kernel(const float* __restrict__ bvec,
                              float* __restrict__ fr,
                              int maskSel, int layer, int c)
{
    const int n = blockIdx.x;
    const int j = blockIdx.y * 128 + threadIdx.x;
    const int sid = n * HID + j;
    const int L = layer - 1;
    const float bj = bvec[j];
    const float* __restrict__ mk = g_maskT[maskSel];
    const size_t cstr = (size_t)NBATCH * HID;
    const float* __restrict__ cPtr = (layer == 2 ? g_C : g_C2) + (size_t)n * HID + j;
    __nv_bfloat16* __restrict__ sOut = g_S2b + (size_t)n * HID + j;
    const int t0 = c * TC;

    float mem, spike, ss;
    if (c == 0){ mem = 0.f; spike = 0.f; ss = 0.f; }
    else { mem = g_mem[L][sid]; spike = g_spk[L][sid]; ss = g_ss[L][sid]; }

    float cb[2][UNR], mb[2][UNR];
    #pragma unroll
    for (int u = 0; u < UNR; ++u){
        cb[0][u] = cPtr[(size_t)(t0 + u) * cstr];
        mb[0][u] = mk[(size_t)(t0 + u) * HID + j];
    }

    for (int tc = 0; tc < TC / UNR; ++tc){
        const int cur = tc & 1, nxt = cur ^ 1;
        const int tb = t0 + tc * UNR;
        if (tc + 1 < TC / UNR){
            #pragma unroll
            for (int u = 0; u < UNR; ++u){
                cb[nxt][u] = cPtr[(size_t)(tb + UNR + u) * cstr];
                mb[nxt][u] = mk[(size_t)(tb + UNR + u) * HID + j];
            }
        }
        #pragma unroll
        for (int u = 0; u < UNR; ++u){
            const float m_t = mb[cur][u];
            const float new_mem = mem * DECAY * (1.f - spike) + cb[cur][u] + bj;
            if (m_t != 0.f) mem = new_mem;
            const float spk = (mem > THRESH) ? m_t : 0.f;
            if (layer == 2) sOut[(size_t)(tb + u) * cstr] = __float2bfloat16(spk);
            ss += spk;
            spike = spk;
        }
    }
    g_mem[L][sid] = mem; g_spk[L][sid] = spike; g_ss[L][sid] = ss;
    if (c == NCHK - 1) fr[sid] = ss * (1.f / (float)T_STEPS);
}

// ---------------------------------------------------------------------------
// Head: outputs[n][oc] = fr3[n] . W4[oc] + b4[oc]
// ---------------------------------------------------------------------------
__global__ void head_kernel(const float* __restrict__ fr3,
                            const float* __restrict__ W4,
                            const float* __restrict__ b4,
                            float* __restrict__ outputs)
{
    const int n = blockIdx.x;
    const int warp = threadIdx.x >> 5;
    const int lane = threadIdx.x & 31;
    const float* __restrict__ f = fr3 + (size_t)n * HID;
    const float* __restrict__ w = W4 + (size_t)warp * HID;
    float s = 0.f;
    for (int j = lane; j < HID; j += 32) s += f[j] * w[j];
#pragma unroll
    for (int o = 16; o > 0; o >>= 1) s += __shfl_xor_sync(0xffffffffu, s, o);
    if (lane == 0) outputs[n * OUTC + warp] = s + b4[warp];
}

// ---------------------------------------------------------------------------
// layer_fr[l] = mean(fr_l)
// ---------------------------------------------------------------------------
__global__ void lfr_kernel(const float* __restrict__ fr_all,
                           float* __restrict__ out3)
{
    const int l = blockIdx.x;
    const float* __restrict__ f = fr_all + (size_t)l * (NBATCH * HID);
    __shared__ float sh[256];
    float s = 0.f;
    for (int idx = threadIdx.x; idx < NBATCH * HID; idx += 256) s += f[idx];
    sh[threadIdx.x] = s;
    __syncthreads();
    for (int o = 128; o > 0; o >>= 1) {
        if (threadIdx.x < o) sh[threadIdx.x] += sh[threadIdx.x + o];
        __syncthreads();
    }
    if (threadIdx.x == 0) out3[l] = sh[0] * (1.f / (float)(NBATCH * HID));
}

// ---------------------------------------------------------------------------
// Launch: two-stream chunked pipeline. Stream 0 (capture stream): GEMMs.
// Stream sB: recurrences + mask transpose. Fork/join + per-chunk events.
// ---------------------------------------------------------------------------
extern "C" void kernel_launch(void* const* d_in, const int* in_sizes, int n_in,
                              void* d_out, int out_size)
{
    const float* x     = (const float*)d_in[0];
    const float* W1    = (const float*)d_in[1];
    const float* b1    = (const float*)d_in[2];
    const float* W2    = (const float*)d_in[3];
    const float* b2    = (const float*)d_in[4];
    const float* W3    = (const float*)d_in[5];
    const float* b3    = (const float*)d_in[6];
    const float* W4    = (const float*)d_in[7];
    const float* b4    = (const float*)d_in[8];
    const float* mask1 = (const float*)d_in[9];
    const float* mask2 = (const float*)d_in[10];
    const float* mask3 = (const float*)d_in[11];

    float* out     = (float*)d_out;
    float* outputs = out;
    float* fr1     = out + NBATCH * OUTC;
    float* fr2     = fr1 + NBATCH * HID;
    float* fr3     = fr2 + NBATCH * HID;
    float* lfr     = fr3 + NBATCH * HID;

    static cudaStream_t sB = nullptr;
    static cudaEvent_t evF, evJ;
    static cudaEvent_t eL1[NCHK], eG1[NCHK], eL2[NCHK], eG2[NCHK];
    if (!sB){
        cudaStreamCreateWithFlags(&sB, cudaStreamNonBlocking);
        cudaEventCreateWithFlags(&evF, cudaEventDisableTiming);
        cudaEventCreateWithFlags(&evJ, cudaEventDisableTiming);
        for (int c = 0; c < NCHK; ++c){
            cudaEventCreateWithFlags(&eL1[c], cudaEventDisableTiming);
            cudaEventCreateWithFlags(&eG1[c], cudaEventDisableTiming);
            cudaEventCreateWithFlags(&eL2[c], cudaEventDisableTiming);
            cudaEventCreateWithFlags(&eG2[c], cudaEventDisableTiming);
        }
        cudaFuncSetAttribute(gemm_bf16, cudaFuncAttributeMaxDynamicSharedMemorySize, GEMM_SMEM);
    }

    dim3 gemm_grid(4, TC);            // per-chunk: 4 n-blocks x 112 t-blocks
    dim3 rec_grid(NBATCH, HID / 128); // 512 CTAs, 128 threads
    dim3 mt_grid(HID / 32, (T_STEPS + 31) / 32, 3);

    // Fork recurrence stream from capture stream
    cudaEventRecord(evF, 0);
    cudaStreamWaitEvent(sB, evF, 0);

    // Stream 0: weight split (GEMMs need it)
    split_kernel<<<(HID*HID + 255)/256, 256>>>(W2, W3);

    // Stream B: mask transpose, then first two L1 chunks
    maskT_kernel<<<mt_grid, dim3(32, 32), 0, sB>>>(mask1, mask2, mask3);
    layer1_kernel<<<rec_grid, 128, 0, sB>>>(x, W1, b1, fr1, 0);
    cudaEventRecord(eL1[0], sB);
    layer1_kernel<<<rec_grid, 128, 0, sB>>>(x, W1, b1, fr1, 1);
    cudaEventRecord(eL1[1], sB);

    // Stream 0: first two G1 chunks
    cudaStreamWaitEvent(0, eL1[0], 0);
    gemm_bf16<<<gemm_grid, 256, GEMM_SMEM>>>(0, 0);
    cudaEventRecord(eG1[0], 0);
    cudaStreamWaitEvent(0, eL1[1], 0);
    gemm_bf16<<<gemm_grid, 256, GEMM_SMEM>>>(0, 1);
    cudaEventRecord(eG1[1], 0);

    for (int c = 0; c < NCHK; ++c){
        // B: L2(c) after G1(c)
        cudaStreamWaitEvent(sB, eG1[c], 0);
        layerR_kernel<<<rec_grid, 128, 0, sB>>>(b2, fr2, 1, 2, c);
        cudaEventRecord(eL2[c], sB);
        // B: L1(c+2) lookahead
        if (c + 2 < NCHK){
            layer1_kernel<<<rec_grid, 128, 0, sB>>>(x, W1, b1, fr1, c + 2);
            cudaEventRecord(eL1[c + 2], sB);
        }
        // 0: G2(c) after L2(c)
        cudaStreamWaitEvent(0, eL2[c], 0);
        gemm_bf16<<<gemm_grid, 256, GEMM_SMEM>>>(1, c);
        cudaEventRecord(eG2[c], 0);
        // 0: G1(c+2) after L1(c+2)
        if (c + 2 < NCHK){
            cudaStreamWaitEvent(0, eL1[c + 2], 0);
            gemm_bf16<<<gemm_grid, 256, GEMM_SMEM>>>(0, c + 2);
            cudaEventRecord(eG1[c + 2], 0);
        }
        // B: L3(c) after G2(c)
        cudaStreamWaitEvent(sB, eG2[c], 0);
        layerR_kernel<<<rec_grid, 128, 0, sB>>>(b3, fr3, 2, 3, c);
    }

    // Join and finish on stream 0
    cudaEventRecord(evJ, sB);
    cudaStreamWaitEvent(0, evJ, 0);
    head_kernel<<<NBATCH, 320>>>(fr3, W4, b4, outputs);
    lfr_kernel<<<3, 256>>>(fr1, lfr);
}

// round 7
// speedup vs baseline: 1.0306x; 1.0306x over previous
#include <cuda_runtime.h>
#include <cuda_bf16.h>
#include <cstdint>
#include <cstddef>

// Problem constants
#define T_STEPS 784
#define NBATCH  128
#define HID     512
#define OUTC    10
#define DECAY   0.2f
#define THRESH  0.5f
#define KDIM    512

// GEMM tiling
#define BM 128
#define BN 128
#define BK 64
#define ROWB 144u              // smem bytes per row: 64 bf16 (128B) + 16B pad
#define TILEB (128u * ROWB)    // 18432 B
#define STAGEB (3u * TILEB)    // A + Wh + Wl per stage
#define GEMM_SMEM (2u * STAGEB + 512u)  // + jrow[128] ints

// Recurrence pipelining
#define UNR 16                 // 784 = 49 * 16

#define SEQ_ELEMS ((size_t)T_STEPS * NBATCH * HID)
__device__ __nv_bfloat16 g_S1b[SEQ_ELEMS];   // layer-1 spikes [t][n][i] (exact 0/1)
__device__ __nv_bfloat16 g_S2b[SEQ_ELEMS];   // layer-2 spikes
__device__ float         g_C  [SEQ_ELEMS];   // GEMM output [t][n][j] fp32 (dense)
__device__ __nv_bfloat16 g_W2h[HID*HID], g_W2l[HID*HID];
__device__ __nv_bfloat16 g_W3h[HID*HID], g_W3l[HID*HID];
__device__ float         g_maskT[3][T_STEPS * HID];   // transposed masks [T][H]
// N-compaction metadata: active output columns per timestep (l=0: mask2, l=1: mask3)
__device__ int g_jl [2][T_STEPS * HID];
__device__ int g_cnt[2][T_STEPS];

// ---------------------------------------------------------------------------
// PTX helpers
// ---------------------------------------------------------------------------
__device__ __forceinline__ uint32_t smem_u32(const void* p){
    uint32_t a;
    asm("{ .reg .u64 t; cvta.to.shared.u64 t, %1; cvt.u32.u64 %0, t; }" : "=r"(a) : "l"(p));
    return a;
}
__device__ __forceinline__ void cp16(uint32_t saddr, const void* gaddr){
    asm volatile("cp.async.cg.shared.global [%0], [%1], 16;" :: "r"(saddr), "l"(gaddr));
}
__device__ __forceinline__ void ldsm4(uint32_t* r, uint32_t addr){
    asm volatile("ldmatrix.sync.aligned.m8n8.x4.shared.b16 {%0,%1,%2,%3}, [%4];"
        : "=r"(r[0]), "=r"(r[1]), "=r"(r[2]), "=r"(r[3]) : "r"(addr));
}
__device__ __forceinline__ void mma_bf16(float* c, const uint32_t* a, const uint32_t* b){
    asm volatile(
        "mma.sync.aligned.m16n8k16.row.col.f32.bf16.bf16.f32 "
        "{%0,%1,%2,%3}, {%4,%5,%6,%7}, {%8,%9}, {%0,%1,%2,%3};"
        : "+f"(c[0]), "+f"(c[1]), "+f"(c[2]), "+f"(c[3])
        : "r"(a[0]), "r"(a[1]), "r"(a[2]), "r"(a[3]), "r"(b[0]), "r"(b[1]));
}

// ---------------------------------------------------------------------------
// Weight split: W -> hi(bf16) + lo(bf16)
// ---------------------------------------------------------------------------
__global__ void split_kernel(const float* __restrict__ W2, const float* __restrict__ W3){
    int idx = blockIdx.x * blockDim.x + threadIdx.x;
    if (idx < HID * HID){
        float w = W2[idx];
        __nv_bfloat16 h = __float2bfloat16(w);
        g_W2h[idx] = h;
        g_W2l[idx] = __float2bfloat16(w - __bfloat162float(h));
        w = W3[idx];
        h = __float2bfloat16(w);
        g_W3h[idx] = h;
        g_W3l[idx] = __float2bfloat16(w - __bfloat162float(h));
    }
}

// ---------------------------------------------------------------------------
// Mask transpose: [H][T] -> [T][H]
// ---------------------------------------------------------------------------
__global__ void maskT_kernel(const float* __restrict__ m1,
                             const float* __restrict__ m2,
                             const float* __restrict__ m3)
{
    __shared__ float tile[32][33];
    const float* src = (blockIdx.z == 0) ? m1 : (blockIdx.z == 1) ? m2 : m3;
    const int jb = blockIdx.x * 32;
    const int tb = blockIdx.y * 32;
    const int tx = threadIdx.x, ty = threadIdx.y;

    if (tb + tx < T_STEPS)
        tile[ty][tx] = src[(size_t)(jb + ty) * T_STEPS + tb + tx];
    __syncthreads();
    if (tb + ty < T_STEPS)
        g_maskT[blockIdx.z][(size_t)(tb + ty) * HID + jb + tx] = tile[tx][ty];
}

// ---------------------------------------------------------------------------
// Active-column compaction: per (t, mask) prefix-scan -> jlist + count.
// grid (T_STEPS, 2), block HID.
// ---------------------------------------------------------------------------
__global__ void compact_kernel(const float* __restrict__ m2,
                               const float* __restrict__ m3)
{
    const int t = blockIdx.x;
    const int l = blockIdx.y;
    const float* __restrict__ src = l ? m3 : m2;
    const int j = threadIdx.x;
    __shared__ int scan[HID];

    const int on = (src[(size_t)j * T_STEPS + t] != 0.f) ? 1 : 0;
    int v = on;
    scan[j] = v;
    __syncthreads();
    #pragma unroll
    for (int o = 1; o < HID; o <<= 1){
        const int add = (j >= o) ? scan[j - o] : 0;
        __syncthreads();
        v += add;
        scan[j] = v;
        __syncthreads();
    }
    if (on) g_jl[l][t * HID + (v - 1)] = j;
    if (j == HID - 1) g_cnt[l][t] = v;
}

// ---------------------------------------------------------------------------
// Layer-1 recurrence, 16-step register double-buffer.
// ---------------------------------------------------------------------------
__global__ void layer1_kernel(const float* __restrict__ x,
                              const float* __restrict__ W1,
                              const float* __restrict__ b1,
                              float* __restrict__ fr1)
{
    const int n = blockIdx.x;
    const int i = blockIdx.y * 128 + threadIdx.x;
    const float w = W1[i];
    const float b = b1[i];
    const float* __restrict__ xr = x + (size_t)n * T_STEPS;
    const float* __restrict__ mk = g_maskT[0];
    __nv_bfloat16* __restrict__ sOut = g_S1b + (size_t)n * HID + i;
    const size_t cstr = (size_t)NBATCH * HID;

    float xb[2][UNR], mb[2][UNR];
    #pragma unroll
    for (int u = 0; u < UNR; ++u){
        xb[0][u] = xr[u];
        mb[0][u] = mk[(size_t)u * HID + i];
    }

    float mem = 0.f, spike = 0.f, ss = 0.f;
    for (int tc = 0; tc < T_STEPS / UNR; ++tc){
        const int cur = tc & 1, nxt = cur ^ 1;
        const int tb = tc * UNR;
        if (tc + 1 < T_STEPS / UNR){
            #pragma unroll
            for (int u = 0; u < UNR; ++u){
                xb[nxt][u] = xr[tb + UNR + u];
                mb[nxt][u] = mk[(size_t)(tb + UNR + u) * HID + i];
            }
        }
        #pragma unroll
        for (int u = 0; u < UNR; ++u){
            const float m_t = mb[cur][u];
            const float new_mem = mem * DECAY * (1.f - spike) + xb[cur][u] * w + b;
            if (m_t != 0.f) mem = new_mem;
            const float spk = (mem > THRESH) ? m_t : 0.f;
            sOut[(size_t)(tb + u) * cstr] = __float2bfloat16(spk);
            ss += spk;
            spike = spk;
        }
    }
    fr1[n * HID + i] = ss * (1.f / (float)T_STEPS);
}

// ---------------------------------------------------------------------------
// bf16 HMMA GEMM, N-compacted: per timestep t (blockIdx.y), compute only the
// active output columns (jlist). B rows gathered via jlist; results scattered
// to the DENSE C layout [t][n][j] (dead columns untouched — never read).
// ---------------------------------------------------------------------------
__global__ void __launch_bounds__(256, 2)
gemm_bf16(int which)
{
    extern __shared__ char smem[];
    const int t = blockIdx.y;
    const int cnt = g_cnt[which][t];
    const int n0 = blockIdx.x * BN;          // pos-space tile base
    if (n0 >= cnt) return;

    const __nv_bfloat16* __restrict__ A  = which ? g_S2b : g_S1b;
    const __nv_bfloat16* __restrict__ Bh = which ? g_W3h : g_W2h;
    const __nv_bfloat16* __restrict__ Bl = which ? g_W3l : g_W2l;
    const int* __restrict__ jl = g_jl[which] + t * HID + n0;

    const uint32_t sb = smem_u32(smem);
    int* jrow_s = (int*)(smem + 2u * STAGEB);
    const int tid  = threadIdx.x;
    const int lane = tid & 31;
    const int wrp  = tid >> 5;
    const int wm   = wrp & 1;          // 2 warp-rows of 64
    const int wn   = wrp >> 1;         // 4 warp-cols of 32
    const int m0 = t * BM;             // rows = (t, n=0..127)
    const int climit = cnt - n0;       // valid local positions

    if (tid < 128) jrow_s[tid] = (tid < climit) ? jl[tid] : 0;
    __syncthreads();

    auto load_stage = [&](int st, int c){
        const uint32_t base = sb + (uint32_t)st * STAGEB;
        #pragma unroll
        for (int i = 0; i < 4; ++i){
            const int q   = tid + 256 * i;
            const int row = q >> 3;
            const int kc  = q & 7;
            const uint32_t soff = (uint32_t)row * ROWB + (uint32_t)kc * 16u;
            const size_t gk = (size_t)c * BK + (size_t)kc * 8;
            const int jr = jrow_s[row];
            cp16(base + soff,             A  + (size_t)(m0 + row) * KDIM + gk);
            cp16(base + TILEB + soff,     Bh + (size_t)jr * KDIM + gk);
            cp16(base + 2u*TILEB + soff,  Bl + (size_t)jr * KDIM + gk);
        }
        asm volatile("cp.async.commit_group;" ::: "memory");
    };

    float acc[4][4][4];
    #pragma unroll
    for (int mi = 0; mi < 4; ++mi)
        #pragma unroll
        for (int ni = 0; ni < 4; ++ni)
            #pragma unroll
            for (int q = 0; q < 4; ++q) acc[mi][ni][q] = 0.f;

    const uint32_t aOff = (uint32_t)(wm * 64 + (lane & 15)) * ROWB
                        + (uint32_t)((lane >> 4) << 3) * 2u;
    const uint32_t bOff = (uint32_t)(wn * 32 + ((lane >> 4) << 3) + (lane & 7)) * ROWB
                        + (uint32_t)(((lane >> 3) & 1) << 4);

    load_stage(0, 0);

    const int NC = KDIM / BK;   // 8
    for (int c = 0; c < NC; ++c){
        if (c + 1 < NC){
            load_stage((c + 1) & 1, c + 1);
            asm volatile("cp.async.wait_group 1;" ::: "memory");
        } else {
            asm volatile("cp.async.wait_group 0;" ::: "memory");
        }
        __syncthreads();

        const uint32_t base = sb + (uint32_t)(c & 1) * STAGEB;
        const uint32_t aB = base + aOff;
        const uint32_t hB = base + TILEB + bOff;
        const uint32_t lB = base + 2u*TILEB + bOff;

        #pragma unroll
        for (int k16 = 0; k16 < 4; ++k16){
            uint32_t a[4][4], bh[2][4], bl[2][4];
            #pragma unroll
            for (int mi = 0; mi < 4; ++mi)
                ldsm4(a[mi], aB + (uint32_t)(mi * 16) * ROWB + (uint32_t)k16 * 32u);
            #pragma unroll
            for (int p = 0; p < 2; ++p){
                ldsm4(bh[p], hB + (uint32_t)(p * 16) * ROWB + (uint32_t)k16 * 32u);
                ldsm4(bl[p], lB + (uint32_t)(p * 16) * ROWB + (uint32_t)k16 * 32u);
            }
            #pragma unroll
            for (int mi = 0; mi < 4; ++mi)
                #pragma unroll
                for (int ni = 0; ni < 4; ++ni){
                    mma_bf16(acc[mi][ni], a[mi], &bh[ni >> 1][(ni & 1) * 2]);
                    mma_bf16(acc[mi][ni], a[mi], &bl[ni >> 1][(ni & 1) * 2]);
                }
        }
        __syncthreads();
    }

    // Scatter epilogue: local pos -> dense column j = jrow_s[pos]; guard pos<climit.
    const int rloc = wm * 64 + (lane >> 2);
    const int pbase = wn * 32 + (lane & 3) * 2;
    #pragma unroll
    for (int mi = 0; mi < 4; ++mi){
        float* row0 = g_C + (size_t)(m0 + rloc + mi * 16) * HID;
        float* row1 = row0 + 8 * HID;
        #pragma unroll
        for (int ni = 0; ni < 4; ++ni){
            const int pl = pbase + ni * 8;
            if (pl < climit){
                const int j0 = jrow_s[pl];
                row0[j0] = acc[mi][ni][0];
                row1[j0] = acc[mi][ni][2];
            }
            if (pl + 1 < climit){
                const int j1 = jrow_s[pl + 1];
                row0[j1] = acc[mi][ni][1];
                row1[j1] = acc[mi][ni][3];
            }
        }
    }
}

// ---------------------------------------------------------------------------
// Layer-2/3 recurrence, 16-step register double-buffer (reads dense C;
// dead-column garbage is loaded but discarded by the mask gate).
// ---------------------------------------------------------------------------
__global__ void layerR_kernel(const float* __restrict__ bvec,
                              float* __restrict__ fr,
                              int maskSel, int layer)
{
    const int n = blockIdx.x;
    const int j = blockIdx.y * 128 + threadIdx.x;
    const float bj = bvec[j];
    const float* __restrict__ mk = g_maskT[maskSel];
    const size_t cstr = (size_t)NBATCH * HID;
    const float* __restrict__ cPtr = g_C + (size_t)n * HID + j;
    __nv_bfloat16* __restrict__ sOut = g_S2b + (size_t)n * HID + j;

    float cb[2][UNR], mb[2][UNR];
    #pragma unroll
    for (int u = 0; u < UNR; ++u){
        cb[0][u] = cPtr[(size_t)u * cstr];
        mb[0][u] = mk[(size_t)u * HID + j];
    }

    float mem = 0.f, spike = 0.f, ss = 0.f;
    for (int tc = 0; tc < T_STEPS / UNR; ++tc){
        const int cur = tc & 1, nxt = cur ^ 1;
        const int tb = tc * UNR;
        if (tc + 1 < T_STEPS / UNR){
            #pragma unroll
            for (int u = 0; u < UNR; ++u){
                cb[nxt][u] = cPtr[(size_t)(tb + UNR + u) * cstr];
                mb[nxt][u] = mk[(size_t)(tb + UNR + u) * HID + j];
            }
        }
        #pragma unroll
        for (int u = 0; u < UNR; ++u){
            const float m_t = mb[cur][u];
            const float new_mem = mem * DECAY * (1.f - spike) + cb[cur][u] + bj;
            if (m_t != 0.f) mem = new_mem;
            const float spk = (mem > THRESH) ? m_t : 0.f;
            if (layer == 2) sOut[(size_t)(tb + u) * cstr] = __float2bfloat16(spk);
            ss += spk;
            spike = spk;
        }
    }
    fr[n * HID + j] = ss * (1.f / (float)T_STEPS);
}

// ---------------------------------------------------------------------------
// Head: outputs[n][oc] = fr3[n] . W4[oc] + b4[oc]
// ---------------------------------------------------------------------------
__global__ void head_kernel(const float* __restrict__ fr3,
                            const float* __restrict__ W4,
                            const float* __restrict__ b4,
                            float* __restrict__ outputs)
{
    const int n = blockIdx.x;
    const int warp = threadIdx.x >> 5;
    const int lane = threadIdx.x & 31;
    const float* __restrict__ f = fr3 + (size_t)n * HID;
    const float* __restrict__ w = W4 + (size_t)warp * HID;
    float s = 0.f;
    for (int j = lane; j < HID; j += 32) s += f[j] * w[j];
#pragma unroll
    for (int o = 16; o > 0; o >>= 1) s += __shfl_xor_sync(0xffffffffu, s, o);
    if (lane == 0) outputs[n * OUTC + warp] = s + b4[warp];
}

// ---------------------------------------------------------------------------
// layer_fr[l] = mean(fr_l)
// ---------------------------------------------------------------------------
__global__ void lfr_kernel(const float* __restrict__ fr_all,
                           float* __restrict__ out3)
{
    const int l = blockIdx.x;
    const float* __restrict__ f = fr_all + (size_t)l * (NBATCH * HID);
    __shared__ float sh[256];
    float s = 0.f;
    for (int idx = threadIdx.x; idx < NBATCH * HID; idx += 256) s += f[idx];
    sh[threadIdx.x] = s;
    __syncthreads();
    for (int o = 128; o > 0; o >>= 1) {
        if (threadIdx.x < o) sh[threadIdx.x] += sh[threadIdx.x + o];
        __syncthreads();
    }
    if (threadIdx.x == 0) out3[l] = sh[0] * (1.f / (float)(NBATCH * HID));
}

// ---------------------------------------------------------------------------
// Launch (serial schedule; chunk overlap reverted — wave quantization regressed)
// ---------------------------------------------------------------------------
extern "C" void kernel_launch(void* const* d_in, const int* in_sizes, int n_in,
                              void* d_out, int out_size)
{
    const float* x     = (const float*)d_in[0];
    const float* W1    = (const float*)d_in[1];
    const float* b1    = (const float*)d_in[2];
    const float* W2    = (const float*)d_in[3];
    const float* b2    = (const float*)d_in[4];
    const float* W3    = (const float*)d_in[5];
    const float* b3    = (const float*)d_in[6];
    const float* W4    = (const float*)d_in[7];
    const float* b4    = (const float*)d_in[8];
    const float* mask1 = (const float*)d_in[9];
    const float* mask2 = (const float*)d_in[10];
    const float* mask3 = (const float*)d_in[11];

    float* out     = (float*)d_out;
    float* outputs = out;
    float* fr1     = out + NBATCH * OUTC;
    float* fr2     = fr1 + NBATCH * HID;
    float* fr3     = fr2 + NBATCH * HID;
    float* lfr     = fr3 + NBATCH * HID;

    cudaFuncSetAttribute(gemm_bf16, cudaFuncAttributeMaxDynamicSharedMemorySize, GEMM_SMEM);

    dim3 gemm_grid(4, T_STEPS);       // x = pos-tile (early-exit past cnt), y = t
    dim3 rec_grid(NBATCH, HID / 128); // 512 CTAs, 128 threads
    dim3 mt_grid(HID / 32, (T_STEPS + 31) / 32, 3);

    maskT_kernel<<<mt_grid, dim3(32, 32)>>>(mask1, mask2, mask3);
    split_kernel<<<(HID*HID + 255)/256, 256>>>(W2, W3);
    compact_kernel<<<dim3(T_STEPS, 2), HID>>>(mask2, mask3);
    layer1_kernel<<<rec_grid, 128>>>(x, W1, b1, fr1);
    gemm_bf16<<<gemm_grid, 256, GEMM_SMEM>>>(0);
    layerR_kernel<<<rec_grid, 128>>>(b2, fr2, 1, 2);
    gemm_bf16<<<gemm_grid, 256, GEMM_SMEM>>>(1);
    layerR_kernel<<<rec_grid, 128>>>(b3, fr3, 2, 3);
    head_kernel<<<NBATCH, 320>>>(fr3, W4, b4, outputs);
    lfr_kernel<<<3, 256>>>(fr1, lfr);
}